// round 2
// baseline (speedup 1.0000x reference)
#include <cuda_runtime.h>

// FASTMultiHeadAttention: Taylor-2 softmax approx with diagonal-gathered RPE.
// B=1, H=8, N=2048, D=64, causal (mask=1).
//
// out[h,i,:] = sum_j w_ij * v[h,j,:] / sum_j w_ij
//   s_ij = q_i . k_j + q_i . rpe[i-j+N-1]
//   w_ij = 1 + s + 0.5 s^2, zeroed for j > i (causal)

constexpr int Hh = 8;
constexpr int Nn = 2048;
constexpr int Dd = 64;
constexpr int BM = 64;
constexpr int BN = 64;
constexpr int NT = Nn / BM;   // 32 i-tiles
constexpr int SST = 68;       // padded row stride (floats) for 64-wide tiles
constexpr int RST = 132;      // padded row stride (floats) for 127-wide rpe band
constexpr int THREADS = 256;

// smem floats: Qs 64x68 | KsT 64x68 | Vs 64x68 | Ws 64x68 | RsT 64x132 | denom 64
constexpr int SMEM_FLOATS = 4 * BM * SST + Dd * RST + 64;

__global__ __launch_bounds__(THREADS, 2)
void fastmax_kernel(const float* __restrict__ q,
                    const float* __restrict__ kg,
                    const float* __restrict__ vg,
                    const float* __restrict__ rpe,
                    const int*   __restrict__ maskp,
                    float*       __restrict__ out)
{
    extern __shared__ float sm[];
    float* Qs     = sm;                  // [64 i][68]  row-major (d along row)
    float* KsT    = Qs  + BM * SST;      // [64 d][68]  transposed (j along row)
    float* Vs     = KsT + Dd * SST;      // [64 j][68]  row-major (d along row)
    float* Ws     = Vs  + BN * SST;      // [64 i][68]  (j along row)
    float* RsT    = Ws  + BM * SST;      // [64 d][132] transposed (band along row)
    float* denomS = RsT + Dd * RST;      // [64]

    const int bx = blockIdx.x;
    const int it = NT - 1 - (bx / Hh);   // heavy tiles first (causal load balance)
    const int h  = bx - (bx / Hh) * Hh;
    const int i0 = it * BM;

    const bool causal = maskp ? (maskp[0] != 0) : true;
    const int  nJ     = causal ? (it + 1) : NT;

    const int tid = threadIdx.x;
    const int tx  = tid & 15;            // j micro-tile (cols tx*4..tx*4+3)
    const int ty  = tid >> 4;            // i micro-tile (rows ty*4..ty*4+3)

    const float* qh = q   + (size_t)h * Nn * Dd;
    const float* kh = kg  + (size_t)h * Nn * Dd;
    const float* vh = vg  + (size_t)h * Nn * Dd;
    float*       oh = out + (size_t)h * Nn * Dd;

    // ---- load Q tile [BM][D], row-major, float4, coalesced ----
    #pragma unroll
    for (int u = 0; u < 4; ++u) {
        int idx = tid + u * THREADS;         // 0..1023
        int r = idx >> 4, c = (idx & 15) * 4;
        float4 val = *(const float4*)(qh + (size_t)(i0 + r) * Dd + c);
        *(float4*)(Qs + r * SST + c) = val;
    }

    float o[4][4] = {};
    float dn[4]   = {};

    for (int jt = 0; jt < nJ; ++jt) {
        const int j0 = jt * BN;
        __syncthreads();   // prev iter's O-GEMM done reading Vs/Ws; Q load done (iter 0)

        // ---- K tile, transposed into KsT[d][j] (conflict-free stores: j contiguous) ----
        #pragma unroll
        for (int u = 0; u < 4; ++u) {
            int idx = tid + u * THREADS;     // (d4, j)
            int j = idx & 63, d4 = idx >> 6;
            float4 val = *(const float4*)(kh + (size_t)(j0 + j) * Dd + d4 * 4);
            KsT[(d4 * 4 + 0) * SST + j] = val.x;
            KsT[(d4 * 4 + 1) * SST + j] = val.y;
            KsT[(d4 * 4 + 2) * SST + j] = val.z;
            KsT[(d4 * 4 + 3) * SST + j] = val.w;
        }
        // ---- V tile, row-major ----
        #pragma unroll
        for (int u = 0; u < 4; ++u) {
            int idx = tid + u * THREADS;
            int r = idx >> 4, c = (idx & 15) * 4;
            float4 val = *(const float4*)(vh + (size_t)(j0 + r) * Dd + c);
            *(float4*)(Vs + r * SST + c) = val;
        }
        // ---- rpe band (127 rows), transposed into RsT[d][band] ----
        // band b (0..126) <-> rel = relMin + b; always within [0, 2N-2].
        const int relMin = i0 - j0 - (BN - 1) + (Nn - 1);
        #pragma unroll
        for (int u = 0; u < 8; ++u) {
            int idx = tid + u * THREADS;     // band = idx&127, d4 = idx>>7
            int band = idx & 127, d4 = idx >> 7;
            if (band < 127) {
                float4 val = *(const float4*)(rpe + (size_t)(relMin + band) * Dd + d4 * 4);
                RsT[(d4 * 4 + 0) * RST + band] = val.x;
                RsT[(d4 * 4 + 1) * RST + band] = val.y;
                RsT[(d4 * 4 + 2) * RST + band] = val.z;
                RsT[(d4 * 4 + 3) * RST + band] = val.w;
            }
        }
        __syncthreads();

        // ---- S phase: s[ii][jj] = sum_d q * (k + rpe_band) ----
        float s[4][4] = {};
        const int base = ty * 4 - tx * 4 + 60;   // aligned float4 col (mult of 4)
        #pragma unroll
        for (int d4 = 0; d4 < 16; ++d4) {
            float4 qf[4];
            #pragma unroll
            for (int ii = 0; ii < 4; ++ii)
                qf[ii] = *(const float4*)(Qs + (ty * 4 + ii) * SST + d4 * 4);
            #pragma unroll
            for (int dd = 0; dd < 4; ++dd) {
                const int d = d4 * 4 + dd;
                float4 kt = *(const float4*)(KsT + d * SST + tx * 4);
                float4 ra = *(const float4*)(RsT + d * RST + base);
                float4 rb = *(const float4*)(RsT + d * RST + base + 4);
                float kk[4] = {kt.x, kt.y, kt.z, kt.w};
                float r8[8] = {ra.x, ra.y, ra.z, ra.w, rb.x, rb.y, rb.z, rb.w};
                #pragma unroll
                for (int ii = 0; ii < 4; ++ii) {
                    float qv = ((const float*)&qf[ii])[dd];
                    #pragma unroll
                    for (int jj = 0; jj < 4; ++jj) {
                        // band idx = (i_loc - j_loc) + 63 = base + (ii - jj + 3)
                        s[ii][jj] = fmaf(qv, kk[jj] + r8[ii - jj + 3], s[ii][jj]);
                    }
                }
            }
        }

        // ---- w = 1 + s + 0.5 s^2, causal mask on diagonal tile, store to Ws ----
        const bool diag = causal && (jt == it);
        #pragma unroll
        for (int ii = 0; ii < 4; ++ii) {
            float4 wrow;
            float* wp = (float*)&wrow;
            #pragma unroll
            for (int jj = 0; jj < 4; ++jj) {
                float sv = s[ii][jj];
                float w  = fmaf(0.5f * sv, sv, 1.0f + sv);
                if (diag && (tx * 4 + jj > ty * 4 + ii)) w = 0.0f;
                wp[jj] = w;
            }
            *(float4*)(Ws + (ty * 4 + ii) * SST + tx * 4) = wrow;
        }
        __syncthreads();

        // ---- O += W @ V ; denom += rowsum(W) (tx==0 lanes only) ----
        #pragma unroll 4
        for (int j4 = 0; j4 < 16; ++j4) {
            float4 wv[4], vf[4];
            #pragma unroll
            for (int ii = 0; ii < 4; ++ii)
                wv[ii] = *(const float4*)(Ws + (ty * 4 + ii) * SST + j4 * 4);
            #pragma unroll
            for (int t = 0; t < 4; ++t)
                vf[t] = *(const float4*)(Vs + (j4 * 4 + t) * SST + tx * 4);
            #pragma unroll
            for (int ii = 0; ii < 4; ++ii) {
                const float* wr = (const float*)&wv[ii];
                #pragma unroll
                for (int t = 0; t < 4; ++t) {
                    float wj = wr[t];
                    const float* vp = (const float*)&vf[t];
                    o[ii][0] = fmaf(wj, vp[0], o[ii][0]);
                    o[ii][1] = fmaf(wj, vp[1], o[ii][1]);
                    o[ii][2] = fmaf(wj, vp[2], o[ii][2]);
                    o[ii][3] = fmaf(wj, vp[3], o[ii][3]);
                }
                if (tx == 0)
                    dn[ii] += wr[0] + wr[1] + wr[2] + wr[3];
            }
        }
    }

    // ---- broadcast denom, divide, write ----
    if (tx == 0) {
        #pragma unroll
        for (int ii = 0; ii < 4; ++ii) denomS[ty * 4 + ii] = dn[ii];
    }
    __syncthreads();
    #pragma unroll
    for (int ii = 0; ii < 4; ++ii) {
        float inv = 1.0f / denomS[ty * 4 + ii];
        float4 res;
        res.x = o[ii][0] * inv;
        res.y = o[ii][1] * inv;
        res.z = o[ii][2] * inv;
        res.w = o[ii][3] * inv;
        *(float4*)(oh + (size_t)(i0 + ty * 4 + ii) * Dd + tx * 4) = res;
    }
}

extern "C" void kernel_launch(void* const* d_in, const int* in_sizes, int n_in,
                              void* d_out, int out_size)
{
    const float* q   = (const float*)d_in[0];
    const float* k   = (const float*)d_in[1];
    const float* v   = (const float*)d_in[2];
    const float* rpe = (const float*)d_in[3];
    const int*   msk = (n_in >= 5) ? (const int*)d_in[4] : nullptr;
    float* out = (float*)d_out;

    const size_t smem = (size_t)SMEM_FLOATS * sizeof(float);  // ~103.7 KB
    cudaFuncSetAttribute(fastmax_kernel,
                         cudaFuncAttributeMaxDynamicSharedMemorySize, (int)smem);
    fastmax_kernel<<<Hh * NT, THREADS, smem>>>(q, k, v, rpe, msk, out);
}

// round 3
// speedup vs baseline: 1.4388x; 1.4388x over previous
#include <cuda_runtime.h>

// FASTMultiHeadAttention: Taylor-2 softmax approx with diagonal-gathered RPE.
// B=1, H=8, N=2048, D=64, causal (mask=1).
//
// Round 3: uniform-work split-K decomposition (CTA = head x i-tile x j-chunk,
// deterministic slab accumulation + finalize), f32x2 packed FMA in O-GEMM.

constexpr int Hh = 8;
constexpr int Nn = 2048;
constexpr int Dd = 64;
constexpr int BM = 64;
constexpr int BN = 64;
constexpr int NT = Nn / BM;   // 32 i-tiles
constexpr int CHUNK = 4;      // j-tiles per CTA
constexpr int MAXC = NT / CHUNK;  // 8 chunk slots per i-tile
constexpr int SST = 68;       // padded row stride (floats) for 64-wide tiles
constexpr int RST = 132;      // padded row stride (floats) for 127-wide rpe band
constexpr int THREADS = 256;

// smem floats: Qs 64x68 | KsT 64x68 | Vs 64x68 | Ws 64x68 | RsT 64x132
constexpr int SMEM_FLOATS = 4 * BM * SST + Dd * RST;

// Deterministic partial-result slabs (exclusive per (c,h,i,[d]) -> no atomics).
__device__ float g_Opart[MAXC * Hh * Nn * Dd];   // ~33.5 MB
__device__ float g_dpart[MAXC * Hh * Nn];        // ~512 KB

typedef unsigned long long ull;

__device__ __forceinline__ ull fma2(ull a, ull b, ull c) {
    ull d;
    asm("fma.rn.f32x2 %0, %1, %2, %3;" : "=l"(d) : "l"(a), "l"(b), "l"(c));
    return d;
}
__device__ __forceinline__ ull pack2(float x, float y) {
    ull d;
    asm("mov.b64 %0, {%1, %2};" : "=l"(d) : "f"(x), "f"(y));
    return d;
}

__global__ __launch_bounds__(THREADS, 2)
void fastmax_kernel(const float* __restrict__ q,
                    const float* __restrict__ kg,
                    const float* __restrict__ vg,
                    const float* __restrict__ rpe,
                    const int*   __restrict__ maskp)
{
    extern __shared__ float sm[];
    float* Qs  = sm;                  // [64 i][68]  row-major (d along row)
    float* KsT = Qs  + BM * SST;      // [64 d][68]  transposed (j along row)
    float* Vs  = KsT + Dd * SST;      // [64 j][68]  row-major (d along row)
    float* Ws  = Vs  + BN * SST;      // [64 i][68]  (j along row)
    float* RsT = Ws  + BM * SST;      // [64 d][132] transposed (band along row)

    // bid -> (it desc, h, c).  grid = 32 * 8 * MAXC = 2048
    const int bx = blockIdx.x;
    const int it = NT - 1 - (bx >> 6);        // 64 = Hh * MAXC
    const int rem = bx & 63;
    const int h  = rem >> 3;
    const int c  = rem & (MAXC - 1);

    const bool causal = maskp ? (maskp[0] != 0) : true;
    const int  nJ  = causal ? (it + 1) : NT;
    const int  jt0 = c * CHUNK;
    if (jt0 >= nJ) return;                    // inactive chunk slot
    const int  jt1 = (jt0 + CHUNK < nJ) ? (jt0 + CHUNK) : nJ;

    const int i0 = it * BM;
    const int tid = threadIdx.x;
    const int tx  = tid & 15;            // j micro-tile (cols tx*4..tx*4+3)
    const int ty  = tid >> 4;            // i micro-tile (rows ty*4..ty*4+3)

    const float* qh = q  + (size_t)h * Nn * Dd;
    const float* kh = kg + (size_t)h * Nn * Dd;
    const float* vh = vg + (size_t)h * Nn * Dd;

    // ---- load Q tile [BM][D], row-major, float4, coalesced ----
    #pragma unroll
    for (int u = 0; u < 4; ++u) {
        int idx = tid + u * THREADS;         // 0..1023
        int r = idx >> 4, cc = (idx & 15) * 4;
        float4 val = *(const float4*)(qh + (size_t)(i0 + r) * Dd + cc);
        *(float4*)(Qs + r * SST + cc) = val;
    }

    ull   o2[4][2] = {};   // packed f32x2 accumulators: rows ii, cols (d0d1),(d2d3)
    float dn[4]    = {};

    for (int jt = jt0; jt < jt1; ++jt) {
        const int j0 = jt * BN;
        __syncthreads();   // prev iter's O-GEMM done reading Vs/Ws; Q load done (iter 0)

        // ---- K tile, transposed into KsT[d][j] ----
        #pragma unroll
        for (int u = 0; u < 4; ++u) {
            int idx = tid + u * THREADS;     // (d4, j)
            int j = idx & 63, d4 = idx >> 6;
            float4 val = *(const float4*)(kh + (size_t)(j0 + j) * Dd + d4 * 4);
            KsT[(d4 * 4 + 0) * SST + j] = val.x;
            KsT[(d4 * 4 + 1) * SST + j] = val.y;
            KsT[(d4 * 4 + 2) * SST + j] = val.z;
            KsT[(d4 * 4 + 3) * SST + j] = val.w;
        }
        // ---- V tile, row-major ----
        #pragma unroll
        for (int u = 0; u < 4; ++u) {
            int idx = tid + u * THREADS;
            int r = idx >> 4, cc = (idx & 15) * 4;
            float4 val = *(const float4*)(vh + (size_t)(j0 + r) * Dd + cc);
            *(float4*)(Vs + r * SST + cc) = val;
        }
        // ---- rpe band (127 rows), transposed into RsT[d][band] ----
        const int relMin = i0 - j0 - (BN - 1) + (Nn - 1);
        #pragma unroll
        for (int u = 0; u < 8; ++u) {
            int idx = tid + u * THREADS;     // band = idx&127, d4 = idx>>7
            int band = idx & 127, d4 = idx >> 7;
            if (band < 127) {
                float4 val = *(const float4*)(rpe + (size_t)(relMin + band) * Dd + d4 * 4);
                RsT[(d4 * 4 + 0) * RST + band] = val.x;
                RsT[(d4 * 4 + 1) * RST + band] = val.y;
                RsT[(d4 * 4 + 2) * RST + band] = val.z;
                RsT[(d4 * 4 + 3) * RST + band] = val.w;
            }
        }
        __syncthreads();

        // ---- S phase: s[ii][jj] = sum_d q * (k + rpe_band) ----
        float s[4][4] = {};
        const int base = ty * 4 - tx * 4 + 60;   // aligned float4 col (mult of 4)
        #pragma unroll
        for (int d4 = 0; d4 < 16; ++d4) {
            float4 qf[4];
            #pragma unroll
            for (int ii = 0; ii < 4; ++ii)
                qf[ii] = *(const float4*)(Qs + (ty * 4 + ii) * SST + d4 * 4);
            #pragma unroll
            for (int dd = 0; dd < 4; ++dd) {
                const int d = d4 * 4 + dd;
                float4 kt = *(const float4*)(KsT + d * SST + tx * 4);
                float4 ra = *(const float4*)(RsT + d * RST + base);
                float4 rb = *(const float4*)(RsT + d * RST + base + 4);
                float kk[4] = {kt.x, kt.y, kt.z, kt.w};
                float r8[8] = {ra.x, ra.y, ra.z, ra.w, rb.x, rb.y, rb.z, rb.w};
                #pragma unroll
                for (int ii = 0; ii < 4; ++ii) {
                    float qv = ((const float*)&qf[ii])[dd];
                    #pragma unroll
                    for (int jj = 0; jj < 4; ++jj) {
                        s[ii][jj] = fmaf(qv, kk[jj] + r8[ii - jj + 3], s[ii][jj]);
                    }
                }
            }
        }

        // ---- w = 1 + s + 0.5 s^2, causal mask on diagonal tile, store to Ws ----
        const bool diag = causal && (jt == it);
        #pragma unroll
        for (int ii = 0; ii < 4; ++ii) {
            float4 wrow;
            float* wp = (float*)&wrow;
            #pragma unroll
            for (int jj = 0; jj < 4; ++jj) {
                float sv = s[ii][jj];
                float w  = fmaf(0.5f * sv, sv, 1.0f + sv);
                if (diag && (tx * 4 + jj > ty * 4 + ii)) w = 0.0f;
                wp[jj] = w;
            }
            *(float4*)(Ws + (ty * 4 + ii) * SST + tx * 4) = wrow;
        }
        __syncthreads();

        // ---- O += W @ V (packed f32x2) ; denom += rowsum(W) (tx==0 lanes) ----
        #pragma unroll 4
        for (int j4 = 0; j4 < 16; ++j4) {
            float4 wv[4];
            ulonglong2 vv[4];
            #pragma unroll
            for (int ii = 0; ii < 4; ++ii)
                wv[ii] = *(const float4*)(Ws + (ty * 4 + ii) * SST + j4 * 4);
            #pragma unroll
            for (int t = 0; t < 4; ++t)
                vv[t] = *(const ulonglong2*)(Vs + (j4 * 4 + t) * SST + tx * 4);
            #pragma unroll
            for (int ii = 0; ii < 4; ++ii) {
                const float* wr = (const float*)&wv[ii];
                #pragma unroll
                for (int t = 0; t < 4; ++t) {
                    ull wp2 = pack2(wr[t], wr[t]);
                    o2[ii][0] = fma2(wp2, vv[t].x, o2[ii][0]);
                    o2[ii][1] = fma2(wp2, vv[t].y, o2[ii][1]);
                }
                if (tx == 0)
                    dn[ii] += wr[0] + wr[1] + wr[2] + wr[3];
            }
        }
    }

    // ---- write unnormalized partials to exclusive slab c (deterministic) ----
    const size_t slabO = ((size_t)(c * Hh + h)) * Nn * Dd;
    const size_t slabD = ((size_t)(c * Hh + h)) * Nn;
    #pragma unroll
    for (int ii = 0; ii < 4; ++ii) {
        union { ull u[2]; float4 f; } cv;
        cv.u[0] = o2[ii][0];
        cv.u[1] = o2[ii][1];
        *(float4*)(g_Opart + slabO + (size_t)(i0 + ty * 4 + ii) * Dd + tx * 4) = cv.f;
    }
    if (tx == 0) {
        #pragma unroll
        for (int ii = 0; ii < 4; ++ii)
            g_dpart[slabD + i0 + ty * 4 + ii] = dn[ii];
    }
}

// Sum slabs in fixed order, divide, write output.
__global__ void finalize_kernel(const int* __restrict__ maskp,
                                float* __restrict__ out)
{
    const bool causal = maskp ? (maskp[0] != 0) : true;
    int idx4 = blockIdx.x * blockDim.x + threadIdx.x;    // float4 index
    int base = idx4 * 4;                                 // element index
    if (base >= Hh * Nn * Dd) return;
    const int h  = base >> 17;           // / (Nn*Dd) = 131072
    const int i  = (base >> 6) & (Nn - 1);
    const int it = i >> 6;
    const int nc = causal ? ((it >> 2) + 1) : MAXC;      // ceil((it+1)/CHUNK)

    float dsum = 0.0f;
    float4 osum = make_float4(0.f, 0.f, 0.f, 0.f);
    for (int cc = 0; cc < nc; ++cc) {
        dsum += g_dpart[((size_t)(cc * Hh + h)) * Nn + i];
        float4 p = *(const float4*)(g_Opart + ((size_t)(cc * Hh + h)) * Nn * Dd + base - (size_t)h * Nn * Dd);
        osum.x += p.x; osum.y += p.y; osum.z += p.z; osum.w += p.w;
    }
    float inv = 1.0f / dsum;
    float4 res = make_float4(osum.x * inv, osum.y * inv, osum.z * inv, osum.w * inv);
    *(float4*)(out + base) = res;
}

extern "C" void kernel_launch(void* const* d_in, const int* in_sizes, int n_in,
                              void* d_out, int out_size)
{
    const float* q   = (const float*)d_in[0];
    const float* k   = (const float*)d_in[1];
    const float* v   = (const float*)d_in[2];
    const float* rpe = (const float*)d_in[3];
    const int*   msk = (n_in >= 5) ? (const int*)d_in[4] : nullptr;
    float* out = (float*)d_out;

    const size_t smem = (size_t)SMEM_FLOATS * sizeof(float);  // ~103.4 KB
    cudaFuncSetAttribute(fastmax_kernel,
                         cudaFuncAttributeMaxDynamicSharedMemorySize, (int)smem);

    fastmax_kernel<<<NT * Hh * MAXC, THREADS, smem>>>(q, k, v, rpe, msk);

    const int total4 = Hh * Nn * Dd / 4;                      // 262144
    finalize_kernel<<<total4 / 256, 256>>>(msk, out);
}

// round 4
// speedup vs baseline: 1.4460x; 1.0050x over previous
#include <cuda_runtime.h>

// FASTMultiHeadAttention: Taylor-2 softmax approx with diagonal-gathered RPE.
// B=1, H=8, N=2048, D=64, causal (mask=1).
//
// Round 3: uniform-work split-K decomposition (CTA = head x i-tile x j-chunk,
// deterministic slab accumulation + finalize), f32x2 packed FMA in O-GEMM.

constexpr int Hh = 8;
constexpr int Nn = 2048;
constexpr int Dd = 64;
constexpr int BM = 64;
constexpr int BN = 64;
constexpr int NT = Nn / BM;   // 32 i-tiles
constexpr int CHUNK = 4;      // j-tiles per CTA
constexpr int MAXC = NT / CHUNK;  // 8 chunk slots per i-tile
constexpr int SST = 68;       // padded row stride (floats) for 64-wide tiles
constexpr int RST = 132;      // padded row stride (floats) for 127-wide rpe band
constexpr int THREADS = 256;

// smem floats: Qs 64x68 | KsT 64x68 | Vs 64x68 | Ws 64x68 | RsT 64x132
constexpr int SMEM_FLOATS = 4 * BM * SST + Dd * RST;

// Deterministic partial-result slabs (exclusive per (c,h,i,[d]) -> no atomics).
__device__ float g_Opart[MAXC * Hh * Nn * Dd];   // ~33.5 MB
__device__ float g_dpart[MAXC * Hh * Nn];        // ~512 KB

typedef unsigned long long ull;

__device__ __forceinline__ ull fma2(ull a, ull b, ull c) {
    ull d;
    asm("fma.rn.f32x2 %0, %1, %2, %3;" : "=l"(d) : "l"(a), "l"(b), "l"(c));
    return d;
}
__device__ __forceinline__ ull pack2(float x, float y) {
    ull d;
    asm("mov.b64 %0, {%1, %2};" : "=l"(d) : "f"(x), "f"(y));
    return d;
}

__global__ __launch_bounds__(THREADS, 2)
void fastmax_kernel(const float* __restrict__ q,
                    const float* __restrict__ kg,
                    const float* __restrict__ vg,
                    const float* __restrict__ rpe,
                    const int*   __restrict__ maskp)
{
    extern __shared__ float sm[];
    float* Qs  = sm;                  // [64 i][68]  row-major (d along row)
    float* KsT = Qs  + BM * SST;      // [64 d][68]  transposed (j along row)
    float* Vs  = KsT + Dd * SST;      // [64 j][68]  row-major (d along row)
    float* Ws  = Vs  + BN * SST;      // [64 i][68]  (j along row)
    float* RsT = Ws  + BM * SST;      // [64 d][132] transposed (band along row)

    // bid -> (it desc, h, c).  grid = 32 * 8 * MAXC = 2048
    const int bx = blockIdx.x;
    const int it = NT - 1 - (bx >> 6);        // 64 = Hh * MAXC
    const int rem = bx & 63;
    const int h  = rem >> 3;
    const int c  = rem & (MAXC - 1);

    const bool causal = maskp ? (maskp[0] != 0) : true;
    const int  nJ  = causal ? (it + 1) : NT;
    const int  jt0 = c * CHUNK;
    if (jt0 >= nJ) return;                    // inactive chunk slot
    const int  jt1 = (jt0 + CHUNK < nJ) ? (jt0 + CHUNK) : nJ;

    const int i0 = it * BM;
    const int tid = threadIdx.x;
    const int tx  = tid & 15;            // j micro-tile (cols tx*4..tx*4+3)
    const int ty  = tid >> 4;            // i micro-tile (rows ty*4..ty*4+3)

    const float* qh = q  + (size_t)h * Nn * Dd;
    const float* kh = kg + (size_t)h * Nn * Dd;
    const float* vh = vg + (size_t)h * Nn * Dd;

    // ---- load Q tile [BM][D], row-major, float4, coalesced ----
    #pragma unroll
    for (int u = 0; u < 4; ++u) {
        int idx = tid + u * THREADS;         // 0..1023
        int r = idx >> 4, cc = (idx & 15) * 4;
        float4 val = *(const float4*)(qh + (size_t)(i0 + r) * Dd + cc);
        *(float4*)(Qs + r * SST + cc) = val;
    }

    ull   o2[4][2] = {};   // packed f32x2 accumulators: rows ii, cols (d0d1),(d2d3)
    float dn[4]    = {};

    for (int jt = jt0; jt < jt1; ++jt) {
        const int j0 = jt * BN;
        __syncthreads();   // prev iter's O-GEMM done reading Vs/Ws; Q load done (iter 0)

        // ---- K tile, transposed into KsT[d][j] ----
        #pragma unroll
        for (int u = 0; u < 4; ++u) {
            int idx = tid + u * THREADS;     // (d4, j)
            int j = idx & 63, d4 = idx >> 6;
            float4 val = *(const float4*)(kh + (size_t)(j0 + j) * Dd + d4 * 4);
            KsT[(d4 * 4 + 0) * SST + j] = val.x;
            KsT[(d4 * 4 + 1) * SST + j] = val.y;
            KsT[(d4 * 4 + 2) * SST + j] = val.z;
            KsT[(d4 * 4 + 3) * SST + j] = val.w;
        }
        // ---- V tile, row-major ----
        #pragma unroll
        for (int u = 0; u < 4; ++u) {
            int idx = tid + u * THREADS;
            int r = idx >> 4, cc = (idx & 15) * 4;
            float4 val = *(const float4*)(vh + (size_t)(j0 + r) * Dd + cc);
            *(float4*)(Vs + r * SST + cc) = val;
        }
        // ---- rpe band (127 rows), transposed into RsT[d][band] ----
        const int relMin = i0 - j0 - (BN - 1) + (Nn - 1);
        #pragma unroll
        for (int u = 0; u < 8; ++u) {
            int idx = tid + u * THREADS;     // band = idx&127, d4 = idx>>7
            int band = idx & 127, d4 = idx >> 7;
            if (band < 127) {
                float4 val = *(const float4*)(rpe + (size_t)(relMin + band) * Dd + d4 * 4);
                RsT[(d4 * 4 + 0) * RST + band] = val.x;
                RsT[(d4 * 4 + 1) * RST + band] = val.y;
                RsT[(d4 * 4 + 2) * RST + band] = val.z;
                RsT[(d4 * 4 + 3) * RST + band] = val.w;
            }
        }
        __syncthreads();

        // ---- S phase: s[ii][jj] = sum_d q * (k + rpe_band) ----
        float s[4][4] = {};
        const int base = ty * 4 - tx * 4 + 60;   // aligned float4 col (mult of 4)
        #pragma unroll
        for (int d4 = 0; d4 < 16; ++d4) {
            float4 qf[4];
            #pragma unroll
            for (int ii = 0; ii < 4; ++ii)
                qf[ii] = *(const float4*)(Qs + (ty * 4 + ii) * SST + d4 * 4);
            #pragma unroll
            for (int dd = 0; dd < 4; ++dd) {
                const int d = d4 * 4 + dd;
                float4 kt = *(const float4*)(KsT + d * SST + tx * 4);
                float4 ra = *(const float4*)(RsT + d * RST + base);
                float4 rb = *(const float4*)(RsT + d * RST + base + 4);
                float kk[4] = {kt.x, kt.y, kt.z, kt.w};
                float r8[8] = {ra.x, ra.y, ra.z, ra.w, rb.x, rb.y, rb.z, rb.w};
                #pragma unroll
                for (int ii = 0; ii < 4; ++ii) {
                    float qv = ((const float*)&qf[ii])[dd];
                    #pragma unroll
                    for (int jj = 0; jj < 4; ++jj) {
                        s[ii][jj] = fmaf(qv, kk[jj] + r8[ii - jj + 3], s[ii][jj]);
                    }
                }
            }
        }

        // ---- w = 1 + s + 0.5 s^2, causal mask on diagonal tile, store to Ws ----
        const bool diag = causal && (jt == it);
        #pragma unroll
        for (int ii = 0; ii < 4; ++ii) {
            float4 wrow;
            float* wp = (float*)&wrow;
            #pragma unroll
            for (int jj = 0; jj < 4; ++jj) {
                float sv = s[ii][jj];
                float w  = fmaf(0.5f * sv, sv, 1.0f + sv);
                if (diag && (tx * 4 + jj > ty * 4 + ii)) w = 0.0f;
                wp[jj] = w;
            }
            *(float4*)(Ws + (ty * 4 + ii) * SST + tx * 4) = wrow;
        }
        __syncthreads();

        // ---- O += W @ V (packed f32x2) ; denom += rowsum(W) (tx==0 lanes) ----
        #pragma unroll 4
        for (int j4 = 0; j4 < 16; ++j4) {
            float4 wv[4];
            ulonglong2 vv[4];
            #pragma unroll
            for (int ii = 0; ii < 4; ++ii)
                wv[ii] = *(const float4*)(Ws + (ty * 4 + ii) * SST + j4 * 4);
            #pragma unroll
            for (int t = 0; t < 4; ++t)
                vv[t] = *(const ulonglong2*)(Vs + (j4 * 4 + t) * SST + tx * 4);
            #pragma unroll
            for (int ii = 0; ii < 4; ++ii) {
                const float* wr = (const float*)&wv[ii];
                #pragma unroll
                for (int t = 0; t < 4; ++t) {
                    ull wp2 = pack2(wr[t], wr[t]);
                    o2[ii][0] = fma2(wp2, vv[t].x, o2[ii][0]);
                    o2[ii][1] = fma2(wp2, vv[t].y, o2[ii][1]);
                }
                if (tx == 0)
                    dn[ii] += wr[0] + wr[1] + wr[2] + wr[3];
            }
        }
    }

    // ---- write unnormalized partials to exclusive slab c (deterministic) ----
    const size_t slabO = ((size_t)(c * Hh + h)) * Nn * Dd;
    const size_t slabD = ((size_t)(c * Hh + h)) * Nn;
    #pragma unroll
    for (int ii = 0; ii < 4; ++ii) {
        union { ull u[2]; float4 f; } cv;
        cv.u[0] = o2[ii][0];
        cv.u[1] = o2[ii][1];
        *(float4*)(g_Opart + slabO + (size_t)(i0 + ty * 4 + ii) * Dd + tx * 4) = cv.f;
    }
    if (tx == 0) {
        #pragma unroll
        for (int ii = 0; ii < 4; ++ii)
            g_dpart[slabD + i0 + ty * 4 + ii] = dn[ii];
    }
}

// Sum slabs in fixed order, divide, write output.
__global__ void finalize_kernel(const int* __restrict__ maskp,
                                float* __restrict__ out)
{
    const bool causal = maskp ? (maskp[0] != 0) : true;
    int idx4 = blockIdx.x * blockDim.x + threadIdx.x;    // float4 index
    int base = idx4 * 4;                                 // element index
    if (base >= Hh * Nn * Dd) return;
    const int h  = base >> 17;           // / (Nn*Dd) = 131072
    const int i  = (base >> 6) & (Nn - 1);
    const int it = i >> 6;
    const int nc = causal ? ((it >> 2) + 1) : MAXC;      // ceil((it+1)/CHUNK)

    float dsum = 0.0f;
    float4 osum = make_float4(0.f, 0.f, 0.f, 0.f);
    for (int cc = 0; cc < nc; ++cc) {
        dsum += g_dpart[((size_t)(cc * Hh + h)) * Nn + i];
        float4 p = *(const float4*)(g_Opart + ((size_t)(cc * Hh + h)) * Nn * Dd + base - (size_t)h * Nn * Dd);
        osum.x += p.x; osum.y += p.y; osum.z += p.z; osum.w += p.w;
    }
    float inv = 1.0f / dsum;
    float4 res = make_float4(osum.x * inv, osum.y * inv, osum.z * inv, osum.w * inv);
    *(float4*)(out + base) = res;
}

extern "C" void kernel_launch(void* const* d_in, const int* in_sizes, int n_in,
                              void* d_out, int out_size)
{
    const float* q   = (const float*)d_in[0];
    const float* k   = (const float*)d_in[1];
    const float* v   = (const float*)d_in[2];
    const float* rpe = (const float*)d_in[3];
    const int*   msk = (n_in >= 5) ? (const int*)d_in[4] : nullptr;
    float* out = (float*)d_out;

    const size_t smem = (size_t)SMEM_FLOATS * sizeof(float);  // ~103.4 KB
    cudaFuncSetAttribute(fastmax_kernel,
                         cudaFuncAttributeMaxDynamicSharedMemorySize, (int)smem);

    fastmax_kernel<<<NT * Hh * MAXC, THREADS, smem>>>(q, k, v, rpe, msk);

    const int total4 = Hh * Nn * Dd / 4;                      // 262144
    finalize_kernel<<<total4 / 256, 256>>>(msk, out);
}

// round 6
// speedup vs baseline: 1.4810x; 1.0242x over previous
#include <cuda_runtime.h>

// FASTMultiHeadAttention via warp-level tf32 mma.sync (base-target PTX, no tcgen05).
// B=1,H=8,N=2048,D=64, causal. s = q.k + q.rpe[i-j+N-1]; w = 1+s+s^2/2; out = Wv/rowsum.
// CTA = (head, 64-row i-tile, chunk of 4 j-tiles). Split-tf32 (hi+lo, 3 MMAs) for fp32-like
// precision. RPE handled as a dedicated QR = Q x R_band^T GEMM + smem diagonal gather.

typedef unsigned int u32;

constexpr int Hh = 8, Nn = 2048, Dd = 64;
constexpr int NT = 32, CHUNK = 4, MAXC = 8, THREADS = 256;
constexpr int SOP = 68;      // operand row stride (floats)
constexpr int QST = 132;     // QR scratch row stride

// smem regions (float offsets)
constexpr int O_Q   = 0;                 // Qs  [64][68]
constexpr int O_K   = 4352;              // Ks  [64][68]  -> reused as Ws
constexpr int O_QRS = 8704;              // QRS [64][132] -> reused as Vs [64][68]
constexpr int O_R   = 17152;             // Rs  [128][68]
constexpr int O_DN  = 25856;             // dnS [64][8]
constexpr int SMEMF = 26368;             // 105472 bytes

__device__ float g_Opart[(size_t)MAXC * Hh * Nn * Dd];   // exclusive partial slabs
__device__ float g_dpart[MAXC * Hh * Nn];

__device__ __forceinline__ void sp32(float x, u32 &h, u32 &l) {
    asm("cvt.rna.tf32.f32 %0, %1;" : "=r"(h) : "f"(x));
    float r = x - __uint_as_float(h);
    asm("cvt.rna.tf32.f32 %0, %1;" : "=r"(l) : "f"(r));
}
__device__ __forceinline__ void mma8(float* c, const u32* a, const u32* b) {
    asm volatile("mma.sync.aligned.m16n8k8.row.col.f32.tf32.tf32.f32 "
        "{%0,%1,%2,%3}, {%4,%5,%6,%7}, {%8,%9}, {%0,%1,%2,%3};"
        : "+f"(c[0]), "+f"(c[1]), "+f"(c[2]), "+f"(c[3])
        : "r"(a[0]), "r"(a[1]), "r"(a[2]), "r"(a[3]), "r"(b[0]), "r"(b[1]));
}
// A fragments (16 rows at r0) from M[row][SOP], k = 0..63; split hi/lo (32+32 regs)
__device__ __forceinline__ void buildA(const float* M, int r0, u32* aH, u32* aL,
                                       int g, int t) {
    #pragma unroll
    for (int k8 = 0; k8 < 8; ++k8) {
        float x0 = M[(r0 + g)     * SOP + k8 * 8 + t];
        float x1 = M[(r0 + g + 8) * SOP + k8 * 8 + t];
        float x2 = M[(r0 + g)     * SOP + k8 * 8 + t + 4];
        float x3 = M[(r0 + g + 8) * SOP + k8 * 8 + t + 4];
        sp32(x0, aH[k8*4+0], aL[k8*4+0]);
        sp32(x1, aH[k8*4+1], aL[k8*4+1]);
        sp32(x2, aH[k8*4+2], aL[k8*4+2]);
        sp32(x3, aH[k8*4+3], aL[k8*4+3]);
    }
}
// C += A x B^T over K=64, B stored [n][SOP] (n-major: K, R). Split: hh + hl + lh.
__device__ __forceinline__ void gemmN(const float* B, int n0, float* c,
                                      const u32* aH, const u32* aL, int g, int t) {
    #pragma unroll
    for (int k8 = 0; k8 < 8; ++k8) {
        float x0 = B[(n0 + g) * SOP + k8 * 8 + t];
        float x1 = B[(n0 + g) * SOP + k8 * 8 + t + 4];
        u32 bh[2], bl[2];
        sp32(x0, bh[0], bl[0]); sp32(x1, bh[1], bl[1]);
        mma8(c, aH + k8 * 4, bh);
        mma8(c, aH + k8 * 4, bl);
        mma8(c, aL + k8 * 4, bh);
    }
}
// C += A x B over K=64, B stored [k][SOP] (k-major: V).
__device__ __forceinline__ void gemmK(const float* B, int n0, float* c,
                                      const u32* aH, const u32* aL, int g, int t) {
    #pragma unroll
    for (int k8 = 0; k8 < 8; ++k8) {
        float x0 = B[(k8 * 8 + t)     * SOP + n0 + g];
        float x1 = B[(k8 * 8 + t + 4) * SOP + n0 + g];
        u32 bh[2], bl[2];
        sp32(x0, bh[0], bl[0]); sp32(x1, bh[1], bl[1]);
        mma8(c, aH + k8 * 4, bh);
        mma8(c, aH + k8 * 4, bl);
        mma8(c, aL + k8 * 4, bh);
    }
}

__global__ __launch_bounds__(THREADS, 2)
void fastmax_mma(const float* __restrict__ q, const float* __restrict__ kg,
                 const float* __restrict__ vg, const float* __restrict__ rpe,
                 const int* __restrict__ maskp)
{
    extern __shared__ float sm[];
    float* Qs  = sm + O_Q;
    float* Ks  = sm + O_K;     // also Ws
    float* QRS = sm + O_QRS;   // also Vs
    float* Rs  = sm + O_R;
    float* dnS = sm + O_DN;

    const int bx = blockIdx.x;
    const int it = NT - 1 - (bx >> 6);
    const int rem = bx & 63;
    const int h = rem >> 3, c = rem & 7;

    const bool causal = maskp ? (maskp[0] != 0) : true;
    const int nJ  = causal ? (it + 1) : NT;
    const int jt0 = c * CHUNK;
    if (jt0 >= nJ) return;
    const int jt1 = (jt0 + CHUNK < nJ) ? (jt0 + CHUNK) : nJ;
    const int i0 = it * 64;

    const int tid = threadIdx.x;
    const int w = tid >> 5, lane = tid & 31;
    const int g = lane >> 2, t = lane & 3;
    const int rb = w >> 1, half = w & 1;     // row-block 0..3, col-half 0..1

    const float* qh = q  + (size_t)h * Nn * Dd;
    const float* kh = kg + (size_t)h * Nn * Dd;
    const float* vh = vg + (size_t)h * Nn * Dd;

    // ---- stage Q [64x64] fp32 ----
    #pragma unroll
    for (int u = 0; u < 4; ++u) {
        int idx = tid + u * THREADS, r = idx >> 4, c4 = (idx & 15) * 4;
        *(float4*)(Qs + r * SOP + c4) = *(const float4*)(qh + (size_t)(i0 + r) * Dd + c4);
    }

    u32 aH[32], aL[32];
    float oc[4][4] = {};
    float dnacc[2] = {0.f, 0.f};

    for (int jt = jt0; jt < jt1; ++jt) {
        const int j0 = jt * 64;
        __syncthreads();                                   // prev O-mma reads done

        // ---- stage K [64x64], R band [127x64] (+zero row) ----
        #pragma unroll
        for (int u = 0; u < 4; ++u) {
            int idx = tid + u * THREADS, r = idx >> 4, c4 = (idx & 15) * 4;
            *(float4*)(Ks + r * SOP + c4) = *(const float4*)(kh + (size_t)(j0 + r) * Dd + c4);
        }
        const int relBase = i0 - j0 + 1984;                // rel = relBase + band, band 0..126
        #pragma unroll
        for (int u = 0; u < 8; ++u) {
            int idx = tid + u * THREADS;
            if (idx < 127 * 16) {
                int r = idx >> 4, c4 = (idx & 15) * 4;
                *(float4*)(Rs + r * SOP + c4) =
                    *(const float4*)(rpe + (size_t)(relBase + r) * Dd + c4);
            }
        }
        if (tid < 16) *(float4*)(Rs + 127 * SOP + tid * 4) = make_float4(0.f, 0.f, 0.f, 0.f);
        __syncthreads();

        // ---- S1 = Q K^T (4 cb per warp) ----
        buildA(Qs, rb * 16, aH, aL, g, t);
        float s1c[4][4] = {};
        #pragma unroll
        for (int ci = 0; ci < 4; ++ci)
            gemmN(Ks, (half * 4 + ci) * 8, s1c[ci], aH, aL, g, t);
        // ---- QR = Q R^T (8 cb per warp), store to QRS ----
        #pragma unroll
        for (int qi = 0; qi < 8; ++qi) {
            int cb = half * 8 + qi;
            float qc[4] = {};
            gemmN(Rs, cb * 8, qc, aH, aL, g, t);
            int rI = rb * 16 + g, jb = cb * 8 + 2 * t;
            *(float2*)(QRS + rI * QST + jb)       = make_float2(qc[0], qc[1]);
            *(float2*)(QRS + (rI + 8) * QST + jb) = make_float2(qc[2], qc[3]);
        }
        __syncthreads();                                   // QRS ready; Ks reads done

        // ---- epilogue: s = s1 + QR[i, i-j+63]; w = 1+s+s^2/2; mask; W -> Ks region ----
        const bool diag = causal && (jt == it);
        #pragma unroll
        for (int ci = 0; ci < 4; ++ci) {
            int cb = half * 4 + ci;
            int rI = rb * 16 + g, jA = cb * 8 + 2 * t;
            #pragma unroll
            for (int e = 0; e < 4; ++e) {
                int row = rI + (e >> 1) * 8;
                int col = jA + (e & 1);
                float s = s1c[ci][e] + QRS[row * QST + (row - col + 63)];
                float wv = fmaf(0.5f * s, s, 1.0f + s);
                if (diag && col > row) wv = 0.0f;
                dnacc[e >> 1] += wv;
                Ks[row * SOP + col] = wv;                  // Ws
            }
        }
        __syncthreads();                                   // QRS reads done; Ws ready

        // ---- stage V into QRS region ----
        float* Vs = QRS;
        #pragma unroll
        for (int u = 0; u < 4; ++u) {
            int idx = tid + u * THREADS, r = idx >> 4, c4 = (idx & 15) * 4;
            *(float4*)(Vs + r * SOP + c4) = *(const float4*)(vh + (size_t)(j0 + r) * Dd + c4);
        }
        __syncthreads();                                   // Vs ready

        // ---- O += W V ----
        buildA(Ks, rb * 16, aH, aL, g, t);
        #pragma unroll
        for (int ci = 0; ci < 4; ++ci)
            gemmK(Vs, (half * 4 + ci) * 8, oc[ci], aH, aL, g, t);
    }

    // ---- deterministic denom reduction + slab writes ----
    dnS[(rb * 16 + g) * 8 + half * 4 + t]     = dnacc[0];
    dnS[(rb * 16 + g + 8) * 8 + half * 4 + t] = dnacc[1];
    __syncthreads();

    const size_t slabO = ((size_t)(c * Hh + h)) * Nn * Dd;
    #pragma unroll
    for (int ci = 0; ci < 4; ++ci) {
        int cb = half * 4 + ci;
        int rI = rb * 16 + g, dc = cb * 8 + 2 * t;
        *(float2*)(g_Opart + slabO + (size_t)(i0 + rI) * Dd + dc) =
            make_float2(oc[ci][0], oc[ci][1]);
        *(float2*)(g_Opart + slabO + (size_t)(i0 + rI + 8) * Dd + dc) =
            make_float2(oc[ci][2], oc[ci][3]);
    }
    if (tid < 64) {
        float s = 0.f;
        #pragma unroll
        for (int k2 = 0; k2 < 8; ++k2) s += dnS[tid * 8 + k2];
        g_dpart[((size_t)(c * Hh + h)) * Nn + i0 + tid] = s;
    }
}

__global__ void finalize_kernel(const int* __restrict__ maskp, float* __restrict__ out)
{
    const bool causal = maskp ? (maskp[0] != 0) : true;
    int base = (blockIdx.x * blockDim.x + threadIdx.x) * 4;
    if (base >= Hh * Nn * Dd) return;
    const int h = base >> 17;
    const int i = (base >> 6) & (Nn - 1);
    const int it = i >> 6;
    const int nc = causal ? ((it >> 2) + 1) : MAXC;
    const int boff = base - h * (Nn * Dd);

    float dsum = 0.0f;
    float4 osum = make_float4(0.f, 0.f, 0.f, 0.f);
    for (int cc = 0; cc < nc; ++cc) {
        size_t s = (size_t)(cc * Hh + h);
        dsum += g_dpart[s * Nn + i];
        float4 p = *(const float4*)(g_Opart + s * Nn * Dd + boff);
        osum.x += p.x; osum.y += p.y; osum.z += p.z; osum.w += p.w;
    }
    float inv = 1.0f / dsum;
    *(float4*)(out + base) = make_float4(osum.x * inv, osum.y * inv, osum.z * inv, osum.w * inv);
}

extern "C" void kernel_launch(void* const* d_in, const int* in_sizes, int n_in,
                              void* d_out, int out_size)
{
    const float* q   = (const float*)d_in[0];
    const float* k   = (const float*)d_in[1];
    const float* v   = (const float*)d_in[2];
    const float* rpe = (const float*)d_in[3];
    const int*   msk = (n_in >= 5) ? (const int*)d_in[4] : nullptr;
    float* out = (float*)d_out;

    const size_t smem = (size_t)SMEMF * sizeof(float);    // 105472 B
    cudaFuncSetAttribute(fastmax_mma, cudaFuncAttributeMaxDynamicSharedMemorySize, (int)smem);
    fastmax_mma<<<NT * Hh * MAXC, THREADS, smem>>>(q, k, v, rpe, msk);
    finalize_kernel<<<(Hh * Nn * Dd / 4) / 256, 256>>>(msk, out);
}

// round 8
// speedup vs baseline: 2.4745x; 1.6709x over previous
#include <cuda_runtime.h>
#include <cuda_bf16.h>

// FASTMultiHeadAttention via mma.sync m16n8k16 bf16 split-precision (hi+lo).
// B=1,H=8,N=2048,D=64, causal. s = q.k + q.rpe[i-j+N-1]; w = 1+s+s^2/2; out = Wv/rowsum.
// CTA = (head, 64-row i-tile, chunk of 4 j-tiles); exclusive slabs + finalize.
// Operands pre-split into packed bf16x2 hi/lo in smem (split once per element).

typedef unsigned int u32;

constexpr int Hh = 8, Nn = 2048, Dd = 64;
constexpr int NT = 32, CHUNK = 4, MAXC = 8, THREADS = 256;
constexpr int MST = 36;    // u32 row stride for bf16x2 matrices (bank = 4g+t, conflict-free)
constexpr int QST = 132;   // QR scratch row stride (floats)

// smem u32 offsets
constexpr int O_QH  = 0,     O_QL  = 2304;        // Q  [64][36] x2
constexpr int O_KH  = 4608,  O_KL  = 6912;        // K  [64][36] x2 (reused as W)
constexpr int O_RH  = 9216,  O_RL  = 13824;       // R  [128][36] x2
constexpr int O_QRS = 18432;                      // QR fp32 [64][132] (Vt overlays)
constexpr int O_VTH = 18432, O_VTL = 20736;       // V^T [64 d][36] x2
constexpr int O_DN  = 26880;                      // dn [64][8] fp32
constexpr int SMEMF = 27392;                      // 109568 bytes

__device__ float g_Opart[(size_t)MAXC * Hh * Nn * Dd];
__device__ float g_dpart[MAXC * Hh * Nn];

// split two floats -> packed bf16x2 hi and lo words (low half = first element)
__device__ __forceinline__ void split2(float a, float b, u32& hi, u32& lo) {
    __nv_bfloat162 h = __floats2bfloat162_rn(a, b);
    float ra = a - __bfloat162float(h.x);
    float rb = b - __bfloat162float(h.y);
    __nv_bfloat162 l = __floats2bfloat162_rn(ra, rb);
    hi = *(u32*)&h; lo = *(u32*)&l;
}
__device__ __forceinline__ void mma16(float* c, const u32* a, const u32* b) {
    asm volatile("mma.sync.aligned.m16n8k16.row.col.f32.bf16.bf16.f32 "
        "{%0,%1,%2,%3},{%4,%5,%6,%7},{%8,%9},{%0,%1,%2,%3};"
        : "+f"(c[0]), "+f"(c[1]), "+f"(c[2]), "+f"(c[3])
        : "r"(a[0]), "r"(a[1]), "r"(a[2]), "r"(a[3]), "r"(b[0]), "r"(b[1]));
}
// A fragments: 16 rows at r0, K=64 -> 4 chunks x 4 regs
__device__ __forceinline__ void ldA(const u32* M, int r0, int g, int t, u32* a) {
    #pragma unroll
    for (int kc = 0; kc < 4; ++kc) {
        a[kc*4+0] = M[(r0 + g)     * MST + kc*8 + t];
        a[kc*4+1] = M[(r0 + g + 8) * MST + kc*8 + t];
        a[kc*4+2] = M[(r0 + g)     * MST + kc*8 + t + 4];
        a[kc*4+3] = M[(r0 + g + 8) * MST + kc*8 + t + 4];
    }
}
// C += A x B^T, split (hh + hl + lh); B stored [n][kp] u32
__device__ __forceinline__ void gemmB(const u32* BH, const u32* BL, int n0, float* c,
                                      const u32* aH, const u32* aL, int g, int t) {
    #pragma unroll
    for (int kc = 0; kc < 4; ++kc) {
        u32 bh[2], bl[2];
        bh[0] = BH[(n0 + g) * MST + kc*8 + t];
        bh[1] = BH[(n0 + g) * MST + kc*8 + t + 4];
        bl[0] = BL[(n0 + g) * MST + kc*8 + t];
        bl[1] = BL[(n0 + g) * MST + kc*8 + t + 4];
        mma16(c, aH + kc*4, bh);
        mma16(c, aH + kc*4, bl);
        mma16(c, aL + kc*4, bh);
    }
}

__global__ __launch_bounds__(THREADS, 2)
void fastmax_mma(const float* __restrict__ q, const float* __restrict__ kg,
                 const float* __restrict__ vg, const float* __restrict__ rpe,
                 const int* __restrict__ maskp)
{
    extern __shared__ u32 smU[];
    float* QRS = (float*)(smU + O_QRS);
    float* dnS = (float*)(smU + O_DN);

    const int bx = blockIdx.x;
    const int it = NT - 1 - (bx >> 6);
    const int rem = bx & 63;
    const int h = rem >> 3, c = rem & 7;

    const bool causal = maskp ? (maskp[0] != 0) : true;
    const int nJ  = causal ? (it + 1) : NT;
    const int jt0 = c * CHUNK;
    if (jt0 >= nJ) return;
    const int jt1 = (jt0 + CHUNK < nJ) ? (jt0 + CHUNK) : nJ;
    const int i0 = it * 64;

    const int tid = threadIdx.x;
    const int w = tid >> 5, lane = tid & 31;
    const int g = lane >> 2, t = lane & 3;
    const int rb = w >> 1, half = w & 1;

    const float* qh = q  + (size_t)h * Nn * Dd;
    const float* kh = kg + (size_t)h * Nn * Dd;
    const float* vh = vg + (size_t)h * Nn * Dd;

    // ---- stage Q (split once) ----
    #pragma unroll
    for (int u = 0; u < 4; ++u) {
        int idx = tid + u * THREADS, r = idx >> 4, c4 = (idx & 15) * 4;
        float4 v = *(const float4*)(qh + (size_t)(i0 + r) * Dd + c4);
        u32 h0, l0, h1, l1; split2(v.x, v.y, h0, l0); split2(v.z, v.w, h1, l1);
        int kp = c4 >> 1;
        *(uint2*)(smU + O_QH + r * MST + kp) = make_uint2(h0, h1);
        *(uint2*)(smU + O_QL + r * MST + kp) = make_uint2(l0, l1);
    }
    __syncthreads();

    // Q A-fragments are loop-invariant: load once
    u32 aQH[16], aQL[16];
    ldA(smU + O_QH, rb * 16, g, t, aQH);
    ldA(smU + O_QL, rb * 16, g, t, aQL);

    float oc[4][4] = {};
    float dnacc[2] = {0.f, 0.f};

    for (int jt = jt0; jt < jt1; ++jt) {
        const int j0 = jt * 64;
        __syncthreads();                       // prev O-GEMM / Q-frag reads done

        // ---- stage K hi/lo ----
        #pragma unroll
        for (int u = 0; u < 4; ++u) {
            int idx = tid + u * THREADS, r = idx >> 4, c4 = (idx & 15) * 4;
            float4 v = *(const float4*)(kh + (size_t)(j0 + r) * Dd + c4);
            u32 h0, l0, h1, l1; split2(v.x, v.y, h0, l0); split2(v.z, v.w, h1, l1);
            int kp = c4 >> 1;
            *(uint2*)(smU + O_KH + r * MST + kp) = make_uint2(h0, h1);
            *(uint2*)(smU + O_KL + r * MST + kp) = make_uint2(l0, l1);
        }
        // ---- stage R band (127 rows + zero row) hi/lo ----
        const int relBase = i0 - j0 + 1984;
        #pragma unroll
        for (int u = 0; u < 8; ++u) {
            int idx = tid + u * THREADS;
            if (idx < 127 * 16) {
                int r = idx >> 4, c4 = (idx & 15) * 4;
                float4 v = *(const float4*)(rpe + (size_t)(relBase + r) * Dd + c4);
                u32 h0, l0, h1, l1; split2(v.x, v.y, h0, l0); split2(v.z, v.w, h1, l1);
                int kp = c4 >> 1;
                *(uint2*)(smU + O_RH + r * MST + kp) = make_uint2(h0, h1);
                *(uint2*)(smU + O_RL + r * MST + kp) = make_uint2(l0, l1);
            }
        }
        if (tid < 16) {
            *(uint2*)(smU + O_RH + 127 * MST + tid * 2) = make_uint2(0, 0);
            *(uint2*)(smU + O_RL + 127 * MST + tid * 2) = make_uint2(0, 0);
        }
        __syncthreads();

        // ---- S1 = Q K^T (4 cb) ----
        float s1c[4][4] = {};
        #pragma unroll
        for (int ci = 0; ci < 4; ++ci)
            gemmB(smU + O_KH, smU + O_KL, (half * 4 + ci) * 8, s1c[ci], aQH, aQL, g, t);
        // ---- QR = Q R^T (8 cb) -> QRS ----
        #pragma unroll
        for (int qi = 0; qi < 8; ++qi) {
            int cb = half * 8 + qi;
            float qc[4] = {};
            gemmB(smU + O_RH, smU + O_RL, cb * 8, qc, aQH, aQL, g, t);
            int rI = rb * 16 + g, jb = cb * 8 + 2 * t;
            *(float2*)(QRS + rI * QST + jb)       = make_float2(qc[0], qc[1]);
            *(float2*)(QRS + (rI + 8) * QST + jb) = make_float2(qc[2], qc[3]);
        }
        __syncthreads();                       // QRS ready; K-frag reads done

        // ---- epilogue: w = 1 + s + s^2/2, mask; split -> W (K region) ----
        const bool diag = causal && (jt == it);
        #pragma unroll
        for (int ci = 0; ci < 4; ++ci) {
            int rI = rb * 16 + g;
            int colA = (half * 4 + ci) * 8 + 2 * t;
            #pragma unroll
            for (int pr = 0; pr < 2; ++pr) {
                int row = rI + pr * 8;
                float sA = s1c[ci][pr*2+0] + QRS[row * QST + (row - colA + 63)];
                float sB = s1c[ci][pr*2+1] + QRS[row * QST + (row - colA + 62)];
                float wA = fmaf(0.5f * sA, sA, 1.0f + sA);
                float wB = fmaf(0.5f * sB, sB, 1.0f + sB);
                if (diag) {
                    if (colA     > row) wA = 0.0f;
                    if (colA + 1 > row) wB = 0.0f;
                }
                dnacc[pr] += wA + wB;
                u32 hi, lo; split2(wA, wB, hi, lo);
                int kp = half * 16 + ci * 4 + t;
                smU[O_KH + row * MST + kp] = hi;
                smU[O_KL + row * MST + kp] = lo;
            }
        }
        __syncthreads();                       // QRS reads done; W ready

        // ---- stage V^T hi/lo into QRS region ----
        #pragma unroll
        for (int u = 0; u < 4; ++u) {
            int idx = tid + u * THREADS, jj = idx >> 4, d4 = (idx & 15) * 4;
            float4 v = *(const float4*)(vh + (size_t)(j0 + jj) * Dd + d4);
            float vv[4] = {v.x, v.y, v.z, v.w};
            __nv_bfloat16* VtH = (__nv_bfloat16*)(smU + O_VTH);
            __nv_bfloat16* VtL = (__nv_bfloat16*)(smU + O_VTL);
            #pragma unroll
            for (int dd = 0; dd < 4; ++dd) {
                __nv_bfloat16 hb = __float2bfloat16_rn(vv[dd]);
                __nv_bfloat16 lb = __float2bfloat16_rn(vv[dd] - __bfloat162float(hb));
                int bi = ((d4 + dd) * MST + (jj >> 1)) * 2 + (jj & 1);
                VtH[bi] = hb; VtL[bi] = lb;
            }
        }
        __syncthreads();                       // Vt ready

        // ---- O += W V ----
        u32 aWH[16], aWL[16];
        ldA(smU + O_KH, rb * 16, g, t, aWH);
        ldA(smU + O_KL, rb * 16, g, t, aWL);
        #pragma unroll
        for (int ci = 0; ci < 4; ++ci)
            gemmB(smU + O_VTH, smU + O_VTL, (half * 4 + ci) * 8, oc[ci], aWH, aWL, g, t);
    }

    // ---- deterministic denom + slab writes ----
    dnS[(rb * 16 + g) * 8 + half * 4 + t]     = dnacc[0];
    dnS[(rb * 16 + g + 8) * 8 + half * 4 + t] = dnacc[1];
    __syncthreads();

    const size_t slabO = ((size_t)(c * Hh + h)) * Nn * Dd;
    #pragma unroll
    for (int ci = 0; ci < 4; ++ci) {
        int rI = rb * 16 + g, dc = (half * 4 + ci) * 8 + 2 * t;
        *(float2*)(g_Opart + slabO + (size_t)(i0 + rI) * Dd + dc) =
            make_float2(oc[ci][0], oc[ci][1]);
        *(float2*)(g_Opart + slabO + (size_t)(i0 + rI + 8) * Dd + dc) =
            make_float2(oc[ci][2], oc[ci][3]);
    }
    if (tid < 64) {
        float s = 0.f;
        #pragma unroll
        for (int k2 = 0; k2 < 8; ++k2) s += dnS[tid * 8 + k2];
        g_dpart[((size_t)(c * Hh + h)) * Nn + i0 + tid] = s;
    }
}

__global__ void finalize_kernel(const int* __restrict__ maskp, float* __restrict__ out)
{
    const bool causal = maskp ? (maskp[0] != 0) : true;
    int base = (blockIdx.x * blockDim.x + threadIdx.x) * 4;
    if (base >= Hh * Nn * Dd) return;
    const int h = base >> 17;
    const int i = (base >> 6) & (Nn - 1);
    const int it = i >> 6;
    const int nc = causal ? ((it >> 2) + 1) : MAXC;
    const int boff = base - h * (Nn * Dd);

    float dsum = 0.0f;
    float4 osum = make_float4(0.f, 0.f, 0.f, 0.f);
    for (int cc = 0; cc < nc; ++cc) {
        size_t s = (size_t)(cc * Hh + h);
        dsum += g_dpart[s * Nn + i];
        float4 p = *(const float4*)(g_Opart + s * Nn * Dd + boff);
        osum.x += p.x; osum.y += p.y; osum.z += p.z; osum.w += p.w;
    }
    float inv = 1.0f / dsum;
    *(float4*)(out + base) = make_float4(osum.x * inv, osum.y * inv, osum.z * inv, osum.w * inv);
}

extern "C" void kernel_launch(void* const* d_in, const int* in_sizes, int n_in,
                              void* d_out, int out_size)
{
    const float* q   = (const float*)d_in[0];
    const float* k   = (const float*)d_in[1];
    const float* v   = (const float*)d_in[2];
    const float* rpe = (const float*)d_in[3];
    const int*   msk = (n_in >= 5) ? (const int*)d_in[4] : nullptr;
    float* out = (float*)d_out;

    const size_t smem = (size_t)SMEMF * sizeof(u32);   // 109568 B
    cudaFuncSetAttribute(fastmax_mma, cudaFuncAttributeMaxDynamicSharedMemorySize, (int)smem);
    fastmax_mma<<<NT * Hh * MAXC, THREADS, smem>>>(q, k, v, rpe, msk);
    finalize_kernel<<<(Hh * Nn * Dd / 4) / 256, 256>>>(msk, out);
}

// round 10
// speedup vs baseline: 2.6996x; 1.0910x over previous
#include <cuda_runtime.h>
#include <cuda_bf16.h>

// FASTMultiHeadAttention via mma.sync m16n8k16 bf16 split-precision (hi+lo).
// R10: same as R9 but QST=82 (even) -- fixes misaligned float2 store.
// W kept in registers (C-frag -> A-frag identity), QR restricted to needed
// bands (5 cb/warp), Vt staged into R region, 4 syncs/tile, per-CTA O reduce.

typedef unsigned int u32;

constexpr int Hh = 8, Nn = 2048, Dd = 64;
constexpr int NT = 32, CHUNK = 4, MAXC = 8, THREADS = 256;
constexpr int MST = 36;    // u32 row stride bf16x2 tiles (bank=4g+t, conflict-free)
constexpr int QST = 82;    // QR local scratch stride (floats, EVEN for float2)

// smem u32 offsets
constexpr int O_QH  = 0,     O_QL  = 2304;   // Q [64][36] x2
constexpr int O_KH  = 4608,  O_KL  = 6912;   // K [64][36] x2
constexpr int O_RH  = 9216,  O_RL  = 13824;  // R [128][36] x2 (reused as V^T)
constexpr int O_QRS = 18432;                 // QR fp32 [64][82] (reused as Ored [64][66])
constexpr int O_DN  = 23680;                 // dn [64][8] fp32
constexpr int SMEMF = 24192;                 // 96768 bytes

__device__ float g_Opart[(size_t)MAXC * Hh * Nn * Dd];
__device__ float g_dpart[MAXC * Hh * Nn];

__device__ __forceinline__ void split2(float a, float b, u32& hi, u32& lo) {
    __nv_bfloat162 h = __floats2bfloat162_rn(a, b);
    float ra = a - __bfloat162float(h.x);
    float rb = b - __bfloat162float(h.y);
    __nv_bfloat162 l = __floats2bfloat162_rn(ra, rb);
    hi = *(u32*)&h; lo = *(u32*)&l;
}
__device__ __forceinline__ void mma16(float* c, const u32* a, const u32* b) {
    asm volatile("mma.sync.aligned.m16n8k16.row.col.f32.bf16.bf16.f32 "
        "{%0,%1,%2,%3},{%4,%5,%6,%7},{%8,%9},{%0,%1,%2,%3};"
        : "+f"(c[0]), "+f"(c[1]), "+f"(c[2]), "+f"(c[3])
        : "r"(a[0]), "r"(a[1]), "r"(a[2]), "r"(a[3]), "r"(b[0]), "r"(b[1]));
}
// A fragments: 16 rows at r0, K=64 -> 4 chunks x 4 regs
__device__ __forceinline__ void ldA(const u32* M, int r0, int g, int t, u32* a) {
    #pragma unroll
    for (int kc = 0; kc < 4; ++kc) {
        a[kc*4+0] = M[(r0 + g)     * MST + kc*8 + t];
        a[kc*4+1] = M[(r0 + g + 8) * MST + kc*8 + t];
        a[kc*4+2] = M[(r0 + g)     * MST + kc*8 + t + 4];
        a[kc*4+3] = M[(r0 + g + 8) * MST + kc*8 + t + 4];
    }
}
// C += A x B^T over K=64, split (hh + hl + lh); B stored [n][k-pairs]
__device__ __forceinline__ void gemmB(const u32* BH, const u32* BL, int n0, float* c,
                                      const u32* aH, const u32* aL, int g, int t) {
    #pragma unroll
    for (int kc = 0; kc < 4; ++kc) {
        u32 bh[2], bl[2];
        int base = (n0 + g) * MST + kc*8 + t;
        bh[0] = BH[base]; bh[1] = BH[base + 4];
        bl[0] = BL[base]; bl[1] = BL[base + 4];
        mma16(c, aH + kc*4, bh);
        mma16(c, aH + kc*4, bl);
        mma16(c, aL + kc*4, bh);
    }
}
// O GEMM: K=32 (warp's j-half), jb = k-pair base offset (half*16)
__device__ __forceinline__ void gemmO(const u32* BH, const u32* BL, int n0, float* c,
                                      const u32* aH, const u32* aL, int g, int t, int jb) {
    #pragma unroll
    for (int kc = 0; kc < 2; ++kc) {
        u32 bh[2], bl[2];
        int base = (n0 + g) * MST + jb + kc*8 + t;
        bh[0] = BH[base]; bh[1] = BH[base + 4];
        bl[0] = BL[base]; bl[1] = BL[base + 4];
        mma16(c, aH + kc*4, bh);
        mma16(c, aH + kc*4, bl);
        mma16(c, aL + kc*4, bh);
    }
}

__global__ __launch_bounds__(THREADS, 2)
void fastmax_mma(const float* __restrict__ q, const float* __restrict__ kg,
                 const float* __restrict__ vg, const float* __restrict__ rpe,
                 const int* __restrict__ maskp)
{
    extern __shared__ u32 smU[];
    float* QRS = (float*)(smU + O_QRS);   // [64][82] local-band QR
    float* dnS = (float*)(smU + O_DN);

    const int bx = blockIdx.x;
    const int it = NT - 1 - (bx >> 6);
    const int rem = bx & 63;
    const int h = rem >> 3, c = rem & 7;

    const bool causal = maskp ? (maskp[0] != 0) : true;
    const int nJ  = causal ? (it + 1) : NT;
    const int jt0 = c * CHUNK;
    if (jt0 >= nJ) return;
    const int jt1 = (jt0 + CHUNK < nJ) ? (jt0 + CHUNK) : nJ;
    const int i0 = it * 64;

    const int tid = threadIdx.x;
    const int w = tid >> 5, lane = tid & 31;
    const int g = lane >> 2, t = lane & 3;
    const int rb = w >> 1, half = w & 1;

    const float* qh = q  + (size_t)h * Nn * Dd;
    const float* kh = kg + (size_t)h * Nn * Dd;
    const float* vh = vg + (size_t)h * Nn * Dd;

    // ---- stage Q (split once) ----
    #pragma unroll
    for (int u = 0; u < 4; ++u) {
        int idx = tid + u * THREADS, r = idx >> 4, c4 = (idx & 15) * 4;
        float4 v = *(const float4*)(qh + (size_t)(i0 + r) * Dd + c4);
        u32 h0, l0, h1, l1; split2(v.x, v.y, h0, l0); split2(v.z, v.w, h1, l1);
        int kp = c4 >> 1;
        *(uint2*)(smU + O_QH + r * MST + kp) = make_uint2(h0, h1);
        *(uint2*)(smU + O_QL + r * MST + kp) = make_uint2(l0, l1);
    }
    __syncthreads();

    u32 aQH[16], aQL[16];
    ldA(smU + O_QH, rb * 16, g, t, aQH);
    ldA(smU + O_QL, rb * 16, g, t, aQL);

    float oc[8][4] = {};                 // O partials over warp's k-half, all 8 d-blocks
    float dnacc[2] = {0.f, 0.f};

    for (int jt = jt0; jt < jt1; ++jt) {
        const int j0 = jt * 64;
        __syncthreads();                 // prev O-GEMM Vt reads done

        // ---- stage K hi/lo ----
        #pragma unroll
        for (int u = 0; u < 4; ++u) {
            int idx = tid + u * THREADS, r = idx >> 4, c4 = (idx & 15) * 4;
            float4 v = *(const float4*)(kh + (size_t)(j0 + r) * Dd + c4);
            u32 h0, l0, h1, l1; split2(v.x, v.y, h0, l0); split2(v.z, v.w, h1, l1);
            int kp = c4 >> 1;
            *(uint2*)(smU + O_KH + r * MST + kp) = make_uint2(h0, h1);
            *(uint2*)(smU + O_KL + r * MST + kp) = make_uint2(l0, l1);
        }
        // ---- stage R band (127 rows + zero row) hi/lo ----
        const int relBase = i0 - j0 + 1984;
        #pragma unroll
        for (int u = 0; u < 8; ++u) {
            int idx = tid + u * THREADS;
            if (idx < 127 * 16) {
                int r = idx >> 4, c4 = (idx & 15) * 4;
                float4 v = *(const float4*)(rpe + (size_t)(relBase + r) * Dd + c4);
                u32 h0, l0, h1, l1; split2(v.x, v.y, h0, l0); split2(v.z, v.w, h1, l1);
                int kp = c4 >> 1;
                *(uint2*)(smU + O_RH + r * MST + kp) = make_uint2(h0, h1);
                *(uint2*)(smU + O_RL + r * MST + kp) = make_uint2(l0, l1);
            }
        }
        if (tid < 16) {
            *(uint2*)(smU + O_RH + 127 * MST + tid * 2) = make_uint2(0, 0);
            *(uint2*)(smU + O_RL + 127 * MST + tid * 2) = make_uint2(0, 0);
        }
        __syncthreads();

        // ---- S1 = Q K^T (4 cb) ----
        float s1c[4][4] = {};
        #pragma unroll
        for (int ci = 0; ci < 4; ++ci)
            gemmB(smU + O_KH, smU + O_KL, (half * 4 + ci) * 8, s1c[ci], aQH, aQL, g, t);
        // ---- QR = Q R^T, only bands [16rb, 16rb+79]: 5 cb per warp ----
        #pragma unroll
        for (int qi = 0; qi < 5; ++qi) {
            int cb = 2 * rb + half * 5 + qi;          // absolute 8-band block
            float qc[4] = {};
            gemmB(smU + O_RH, smU + O_RL, cb * 8, qc, aQH, aQL, g, t);
            int rI = rb * 16 + g;
            int jb = 8 * (half * 5 + qi) + 2 * t;     // local band offset
            *(float2*)(QRS + rI * QST + jb)       = make_float2(qc[0], qc[1]);
            *(float2*)(QRS + (rI + 8) * QST + jb) = make_float2(qc[2], qc[3]);
        }
        __syncthreads();                 // QRS ready; K/R frag reads done

        // ---- epilogue: w in regs -> A-fragments (C->A identity); dn; mask ----
        const bool diag = causal && (jt == it);
        u32 aWH[8], aWL[8];
        #pragma unroll
        for (int ci = 0; ci < 4; ++ci) {
            int colA = (half * 4 + ci) * 8 + 2 * t;   // absolute j in tile
            float wv[4];
            #pragma unroll
            for (int pr = 0; pr < 2; ++pr) {
                int row = rb * 16 + g + pr * 8;
                int lb  = g + pr * 8 - colA + 63;     // local band
                float sA = s1c[ci][pr*2+0] + QRS[row * QST + lb];
                float sB = s1c[ci][pr*2+1] + QRS[row * QST + lb - 1];
                float wA = fmaf(0.5f * sA, sA, 1.0f + sA);
                float wB = fmaf(0.5f * sB, sB, 1.0f + sB);
                if (diag) {
                    if (colA     > row) wA = 0.0f;
                    if (colA + 1 > row) wB = 0.0f;
                }
                dnacc[pr] += wA + wB;
                wv[pr*2+0] = wA; wv[pr*2+1] = wB;
            }
            int ai = (ci >> 1) * 4 + (ci & 1) * 2;
            split2(wv[0], wv[1], aWH[ai],     aWL[ai]);
            split2(wv[2], wv[3], aWH[ai + 1], aWL[ai + 1]);
        }
        // ---- stage V^T hi/lo into R region ----
        {
            __nv_bfloat16* VtH = (__nv_bfloat16*)(smU + O_RH);
            __nv_bfloat16* VtL = (__nv_bfloat16*)(smU + O_RL);
            #pragma unroll
            for (int u = 0; u < 4; ++u) {
                int idx = tid + u * THREADS, jj = idx >> 4, d4 = (idx & 15) * 4;
                float4 v = *(const float4*)(vh + (size_t)(j0 + jj) * Dd + d4);
                float vv[4] = {v.x, v.y, v.z, v.w};
                #pragma unroll
                for (int dd = 0; dd < 4; ++dd) {
                    __nv_bfloat16 hb = __float2bfloat16_rn(vv[dd]);
                    __nv_bfloat16 lb = __float2bfloat16_rn(vv[dd] - __bfloat162float(hb));
                    int bi = ((d4 + dd) * MST + (jj >> 1)) * 2 + (jj & 1);
                    VtH[bi] = hb; VtL[bi] = lb;
                }
            }
        }
        __syncthreads();                 // Vt ready; QRS reads done

        // ---- O += W(regs) x V over warp's k-half, all 8 d-blocks ----
        #pragma unroll
        for (int cb = 0; cb < 8; ++cb)
            gemmO(smU + O_RH, smU + O_RL, cb * 8, oc[cb], aWH, aWL, g, t, half * 16);
    }

    // ---- cross-half O reduce + deterministic denom + slab writes ----
    dnS[(rb * 16 + g) * 8 + half * 4 + t]     = dnacc[0];
    dnS[(rb * 16 + g + 8) * 8 + half * 4 + t] = dnacc[1];
    float* Ored = (float*)(smU + O_QRS);      // [64][66]
    if (half == 1) {
        #pragma unroll
        for (int cb = 0; cb < 8; ++cb) {
            *(float2*)(Ored + (rb*16 + g) * 66 + cb*8 + 2*t)     = make_float2(oc[cb][0], oc[cb][1]);
            *(float2*)(Ored + (rb*16 + g + 8) * 66 + cb*8 + 2*t) = make_float2(oc[cb][2], oc[cb][3]);
        }
    }
    __syncthreads();

    const size_t slabO = ((size_t)(c * Hh + h)) * Nn * Dd;
    if (half == 0) {
        #pragma unroll
        for (int cb = 0; cb < 8; ++cb) {
            float2 r0 = *(float2*)(Ored + (rb*16 + g) * 66 + cb*8 + 2*t);
            float2 r1 = *(float2*)(Ored + (rb*16 + g + 8) * 66 + cb*8 + 2*t);
            *(float2*)(g_Opart + slabO + (size_t)(i0 + rb*16 + g) * Dd + cb*8 + 2*t) =
                make_float2(oc[cb][0] + r0.x, oc[cb][1] + r0.y);
            *(float2*)(g_Opart + slabO + (size_t)(i0 + rb*16 + g + 8) * Dd + cb*8 + 2*t) =
                make_float2(oc[cb][2] + r1.x, oc[cb][3] + r1.y);
        }
    }
    if (tid < 64) {
        float s = 0.f;
        #pragma unroll
        for (int k2 = 0; k2 < 8; ++k2) s += dnS[tid * 8 + k2];
        g_dpart[((size_t)(c * Hh + h)) * Nn + i0 + tid] = s;
    }
}

__global__ void finalize_kernel(const int* __restrict__ maskp, float* __restrict__ out)
{
    const bool causal = maskp ? (maskp[0] != 0) : true;
    int base = (blockIdx.x * blockDim.x + threadIdx.x) * 4;
    if (base >= Hh * Nn * Dd) return;
    const int h = base >> 17;
    const int i = (base >> 6) & (Nn - 1);
    const int it = i >> 6;
    const int nc = causal ? ((it >> 2) + 1) : MAXC;
    const int boff = base - h * (Nn * Dd);

    float dsum = 0.0f;
    float4 osum = make_float4(0.f, 0.f, 0.f, 0.f);
    for (int cc = 0; cc < nc; ++cc) {
        size_t s = (size_t)(cc * Hh + h);
        dsum += g_dpart[s * Nn + i];
        float4 p = *(const float4*)(g_Opart + s * Nn * Dd + boff);
        osum.x += p.x; osum.y += p.y; osum.z += p.z; osum.w += p.w;
    }
    float inv = 1.0f / dsum;
    *(float4*)(out + base) = make_float4(osum.x * inv, osum.y * inv, osum.z * inv, osum.w * inv);
}

extern "C" void kernel_launch(void* const* d_in, const int* in_sizes, int n_in,
                              void* d_out, int out_size)
{
    const float* q   = (const float*)d_in[0];
    const float* k   = (const float*)d_in[1];
    const float* v   = (const float*)d_in[2];
    const float* rpe = (const float*)d_in[3];
    const int*   msk = (n_in >= 5) ? (const int*)d_in[4] : nullptr;
    float* out = (float*)d_out;

    const size_t smem = (size_t)SMEMF * sizeof(u32);   // 96768 B
    cudaFuncSetAttribute(fastmax_mma, cudaFuncAttributeMaxDynamicSharedMemorySize, (int)smem);
    fastmax_mma<<<NT * Hh * MAXC, THREADS, smem>>>(q, k, v, rpe, msk);
    finalize_kernel<<<(Hh * Nn * Dd / 4) / 256, 256>>>(msk, out);
}

// round 11
// speedup vs baseline: 2.9787x; 1.1034x over previous
#include <cuda_runtime.h>
#include <cuda_bf16.h>

// FASTMultiHeadAttention via mma.sync m16n8k16 bf16 split-precision (hi+lo).
// R11: 128-row supertiles (512 thr, 16 warps), chunk-persistent R band staged
// once per CTA, K-staging overlapped with prior O-GEMM, 7 syncs/CTA.

typedef unsigned int u32;

constexpr int Hh = 8, Nn = 2048, Dd = 64;
constexpr int NSUP = 16, MAXC = 16, THREADS = 512;
constexpr int MST = 36;    // u32 row stride bf16x2 tiles
constexpr int QST = 82;    // QRS stride (floats, even)
constexpr int OST = 66;    // Ored stride

// smem u32 offsets
constexpr int O_QH = 0,     O_QL = 4608;    // Q [128][36] x2
constexpr int O_KH = 9216,  O_KL = 11520;   // K [64][36] x2
constexpr int O_RH = 13824, O_RL = 23040;   // R [256][36] x2 (chunk-persistent)
constexpr int O_VTH = 32256, O_VTL = 34560; // V^T [64][36] x2
constexpr int O_QRS = 36864;                // [128][82] f32 (Ored [128][66] overlay)
constexpr int O_DN = 47360;                 // [128][8] f32
constexpr int SMEMF = 48384;                // 193536 B

__device__ float g_Opart[(size_t)MAXC * Hh * Nn * Dd];
__device__ float g_dpart[MAXC * Hh * Nn];

__device__ __forceinline__ void split2(float a, float b, u32& hi, u32& lo) {
    __nv_bfloat162 h = __floats2bfloat162_rn(a, b);
    float ra = a - __bfloat162float(h.x);
    float rb = b - __bfloat162float(h.y);
    __nv_bfloat162 l = __floats2bfloat162_rn(ra, rb);
    hi = *(u32*)&h; lo = *(u32*)&l;
}
__device__ __forceinline__ void mma16(float* c, const u32* a, const u32* b) {
    asm volatile("mma.sync.aligned.m16n8k16.row.col.f32.bf16.bf16.f32 "
        "{%0,%1,%2,%3},{%4,%5,%6,%7},{%8,%9},{%0,%1,%2,%3};"
        : "+f"(c[0]), "+f"(c[1]), "+f"(c[2]), "+f"(c[3])
        : "r"(a[0]), "r"(a[1]), "r"(a[2]), "r"(a[3]), "r"(b[0]), "r"(b[1]));
}
__device__ __forceinline__ void ldA(const u32* M, int r0, int g, int t, u32* a) {
    #pragma unroll
    for (int kc = 0; kc < 4; ++kc) {
        a[kc*4+0] = M[(r0 + g)     * MST + kc*8 + t];
        a[kc*4+1] = M[(r0 + g + 8) * MST + kc*8 + t];
        a[kc*4+2] = M[(r0 + g)     * MST + kc*8 + t + 4];
        a[kc*4+3] = M[(r0 + g + 8) * MST + kc*8 + t + 4];
    }
}
__device__ __forceinline__ void gemmB(const u32* BH, const u32* BL, int n0, float* c,
                                      const u32* aH, const u32* aL, int g, int t) {
    #pragma unroll
    for (int kc = 0; kc < 4; ++kc) {
        u32 bh[2], bl[2];
        int base = (n0 + g) * MST + kc*8 + t;
        bh[0] = BH[base]; bh[1] = BH[base + 4];
        bl[0] = BL[base]; bl[1] = BL[base + 4];
        mma16(c, aH + kc*4, bh);
        mma16(c, aH + kc*4, bl);
        mma16(c, aL + kc*4, bh);
    }
}
__device__ __forceinline__ void gemmO(const u32* BH, const u32* BL, int n0, float* c,
                                      const u32* aH, const u32* aL, int g, int t, int jb) {
    #pragma unroll
    for (int kc = 0; kc < 2; ++kc) {
        u32 bh[2], bl[2];
        int base = (n0 + g) * MST + jb + kc*8 + t;
        bh[0] = BH[base]; bh[1] = BH[base + 4];
        bl[0] = BL[base]; bl[1] = BL[base + 4];
        mma16(c, aH + kc*4, bh);
        mma16(c, aH + kc*4, bl);
        mma16(c, aL + kc*4, bh);
    }
}

__global__ __launch_bounds__(THREADS, 1)
void fastmax_mma(const float* __restrict__ q, const float* __restrict__ kg,
                 const float* __restrict__ vg, const float* __restrict__ rpe,
                 const int* __restrict__ maskp)
{
    extern __shared__ u32 smU[];
    float* QRS = (float*)(smU + O_QRS);
    float* dnS = (float*)(smU + O_DN);

    const int bx = blockIdx.x;
    const int ts = NSUP - 1 - (bx >> 7);        // supertile, heavy-first
    const int rem = bx & 127;
    const int cs = rem >> 3, h = rem & 7;

    const bool causal = maskp ? (maskp[0] != 0) : true;
    if (causal && cs > ts) return;
    const int i0 = ts * 128;
    const bool diagC = causal && (cs == ts);
    const int rel0 = 128 * (ts - cs) + 1920;    // in [0, 3840]

    const int tid = threadIdx.x;
    const int w = tid >> 5, lane = tid & 31;
    const int g = lane >> 2, t = lane & 3;
    const int rb = w >> 1, half = w & 1;        // rb in [0,7]

    const float* qh = q  + (size_t)h * Nn * Dd;
    const float* kh = kg + (size_t)h * Nn * Dd;
    const float* vh = vg + (size_t)h * Nn * Dd;

    // ---- stage Q [128x64] hi/lo ----
    #pragma unroll
    for (int u = 0; u < 4; ++u) {
        int idx = tid + u * THREADS, r = idx >> 4, c4 = (idx & 15) * 4;
        float4 v = *(const float4*)(qh + (size_t)(i0 + r) * Dd + c4);
        u32 h0, l0, h1, l1; split2(v.x, v.y, h0, l0); split2(v.z, v.w, h1, l1);
        int kp = c4 >> 1;
        *(uint2*)(smU + O_QH + r * MST + kp) = make_uint2(h0, h1);
        *(uint2*)(smU + O_QL + r * MST + kp) = make_uint2(l0, l1);
    }
    // ---- stage R band [255x64] once per CTA (+zero row 255) ----
    #pragma unroll
    for (int u = 0; u < 8; ++u) {
        int idx = tid + u * THREADS;
        if (idx < 255 * 16) {
            int r = idx >> 4, c4 = (idx & 15) * 4;
            float4 v = *(const float4*)(rpe + (size_t)(rel0 + r) * Dd + c4);
            u32 h0, l0, h1, l1; split2(v.x, v.y, h0, l0); split2(v.z, v.w, h1, l1);
            int kp = c4 >> 1;
            *(uint2*)(smU + O_RH + r * MST + kp) = make_uint2(h0, h1);
            *(uint2*)(smU + O_RL + r * MST + kp) = make_uint2(l0, l1);
        }
    }
    if (tid < 32) {
        smU[O_RH + 255 * MST + tid] = 0;
        smU[O_RL + 255 * MST + tid] = 0;
    }
    __syncthreads();

    u32 aQH[16], aQL[16];
    ldA(smU + O_QH, rb * 16, g, t, aQH);
    ldA(smU + O_QL, rb * 16, g, t, aQL);

    float oc[8][4] = {};
    float dnacc[2] = {0.f, 0.f};

    #pragma unroll
    for (int tl = 0; tl < 2; ++tl) {
        const int j0 = cs * 128 + tl * 64;
        // ---- stage K hi/lo (overlaps prior O-GEMM; regions disjoint) ----
        #pragma unroll
        for (int u = 0; u < 2; ++u) {
            int idx = tid + u * THREADS, r = idx >> 4, c4 = (idx & 15) * 4;
            float4 v = *(const float4*)(kh + (size_t)(j0 + r) * Dd + c4);
            u32 h0, l0, h1, l1; split2(v.x, v.y, h0, l0); split2(v.z, v.w, h1, l1);
            int kp = c4 >> 1;
            *(uint2*)(smU + O_KH + r * MST + kp) = make_uint2(h0, h1);
            *(uint2*)(smU + O_KL + r * MST + kp) = make_uint2(l0, l1);
        }
        __syncthreads();                       // K ready (also: all prior O-GEMM done)

        // ---- S1 = Q K^T ----
        float s1c[4][4] = {};
        #pragma unroll
        for (int ci = 0; ci < 4; ++ci)
            gemmB(smU + O_KH, smU + O_KL, (half * 4 + ci) * 8, s1c[ci], aQH, aQL, g, t);
        // ---- QR = Q R^T, bands [16rb, 16rb+79], step offset 64(1-tl) ----
        const int roff = 64 * (1 - tl);
        #pragma unroll
        for (int qi = 0; qi < 5; ++qi) {
            int cb = 2 * rb + half * 5 + qi;
            float qc[4] = {};
            gemmB(smU + O_RH, smU + O_RL, cb * 8 + roff, qc, aQH, aQL, g, t);
            int rI = rb * 16 + g;
            int jb = 8 * (half * 5 + qi) + 2 * t;
            *(float2*)(QRS + rI * QST + jb)       = make_float2(qc[0], qc[1]);
            *(float2*)(QRS + (rI + 8) * QST + jb) = make_float2(qc[2], qc[3]);
        }
        __syncthreads();                       // QRS ready; K/R frag reads done

        // ---- epilogue: w in regs -> A-frags; dn; mask ----
        u32 aWH[8], aWL[8];
        #pragma unroll
        for (int ci = 0; ci < 4; ++ci) {
            int colA = (half * 4 + ci) * 8 + 2 * t;   // j within the 64-col step
            float wv[4];
            #pragma unroll
            for (int pr = 0; pr < 2; ++pr) {
                int row = rb * 16 + g + pr * 8;       // i within 128-row supertile
                int jb  = g + pr * 8 - colA + 63;     // local band
                float sA = s1c[ci][pr*2+0] + QRS[row * QST + jb];
                float sB = s1c[ci][pr*2+1] + QRS[row * QST + jb - 1];
                float wA = fmaf(0.5f * sA, sA, 1.0f + sA);
                float wB = fmaf(0.5f * sB, sB, 1.0f + sB);
                if (diagC) {
                    if (tl * 64 + colA     > row) wA = 0.0f;
                    if (tl * 64 + colA + 1 > row) wB = 0.0f;
                }
                dnacc[pr] += wA + wB;
                wv[pr*2+0] = wA; wv[pr*2+1] = wB;
            }
            int ai = (ci >> 1) * 4 + (ci & 1) * 2;
            split2(wv[0], wv[1], aWH[ai],     aWL[ai]);
            split2(wv[2], wv[3], aWH[ai + 1], aWL[ai + 1]);
        }
        // ---- stage V^T hi/lo ----
        {
            __nv_bfloat16* VtH = (__nv_bfloat16*)(smU + O_VTH);
            __nv_bfloat16* VtL = (__nv_bfloat16*)(smU + O_VTL);
            #pragma unroll
            for (int u = 0; u < 2; ++u) {
                int idx = tid + u * THREADS, jj = idx >> 4, d4 = (idx & 15) * 4;
                float4 v = *(const float4*)(vh + (size_t)(j0 + jj) * Dd + d4);
                float vv[4] = {v.x, v.y, v.z, v.w};
                #pragma unroll
                for (int dd = 0; dd < 4; ++dd) {
                    __nv_bfloat16 hb = __float2bfloat16_rn(vv[dd]);
                    __nv_bfloat16 lb = __float2bfloat16_rn(vv[dd] - __bfloat162float(hb));
                    int bi = ((d4 + dd) * MST + (jj >> 1)) * 2 + (jj & 1);
                    VtH[bi] = hb; VtL[bi] = lb;
                }
            }
        }
        __syncthreads();                       // Vt ready; QRS reads done

        // ---- O += W(regs) x V over warp's j-half, all 8 d-blocks ----
        #pragma unroll
        for (int cb = 0; cb < 8; ++cb)
            gemmO(smU + O_VTH, smU + O_VTL, cb * 8, oc[cb], aWH, aWL, g, t, half * 16);
    }

    // ---- cross-half O reduce + denom + slab writes ----
    dnS[(rb * 16 + g) * 8 + half * 4 + t]     = dnacc[0];
    dnS[(rb * 16 + g + 8) * 8 + half * 4 + t] = dnacc[1];
    float* Ored = (float*)(smU + O_QRS);       // [128][66] overlay (QRS reads done)
    if (half == 1) {
        #pragma unroll
        for (int cb = 0; cb < 8; ++cb) {
            *(float2*)(Ored + (rb*16 + g) * OST + cb*8 + 2*t)     = make_float2(oc[cb][0], oc[cb][1]);
            *(float2*)(Ored + (rb*16 + g + 8) * OST + cb*8 + 2*t) = make_float2(oc[cb][2], oc[cb][3]);
        }
    }
    __syncthreads();

    const size_t slabO = ((size_t)(cs * Hh + h)) * Nn * Dd;
    if (half == 0) {
        #pragma unroll
        for (int cb = 0; cb < 8; ++cb) {
            float2 r0 = *(float2*)(Ored + (rb*16 + g) * OST + cb*8 + 2*t);
            float2 r1 = *(float2*)(Ored + (rb*16 + g + 8) * OST + cb*8 + 2*t);
            *(float2*)(g_Opart + slabO + (size_t)(i0 + rb*16 + g) * Dd + cb*8 + 2*t) =
                make_float2(oc[cb][0] + r0.x, oc[cb][1] + r0.y);
            *(float2*)(g_Opart + slabO + (size_t)(i0 + rb*16 + g + 8) * Dd + cb*8 + 2*t) =
                make_float2(oc[cb][2] + r1.x, oc[cb][3] + r1.y);
        }
    }
    if (tid < 128) {
        float s = 0.f;
        #pragma unroll
        for (int k2 = 0; k2 < 8; ++k2) s += dnS[tid * 8 + k2];
        g_dpart[((size_t)(cs * Hh + h)) * Nn + i0 + tid] = s;
    }
}

__global__ void finalize_kernel(const int* __restrict__ maskp, float* __restrict__ out)
{
    const bool causal = maskp ? (maskp[0] != 0) : true;
    int base = (blockIdx.x * blockDim.x + threadIdx.x) * 4;
    if (base >= Hh * Nn * Dd) return;
    const int h = base >> 17;
    const int i = (base >> 6) & (Nn - 1);
    const int nc = causal ? ((i >> 7) + 1) : MAXC;
    const int boff = base - h * (Nn * Dd);

    float dsum = 0.0f;
    float4 osum = make_float4(0.f, 0.f, 0.f, 0.f);
    for (int cc = 0; cc < nc; ++cc) {
        size_t s = (size_t)(cc * Hh + h);
        dsum += g_dpart[s * Nn + i];
        float4 p = *(const float4*)(g_Opart + s * Nn * Dd + boff);
        osum.x += p.x; osum.y += p.y; osum.z += p.z; osum.w += p.w;
    }
    float inv = 1.0f / dsum;
    *(float4*)(out + base) = make_float4(osum.x * inv, osum.y * inv, osum.z * inv, osum.w * inv);
}

extern "C" void kernel_launch(void* const* d_in, const int* in_sizes, int n_in,
                              void* d_out, int out_size)
{
    const float* q   = (const float*)d_in[0];
    const float* k   = (const float*)d_in[1];
    const float* v   = (const float*)d_in[2];
    const float* rpe = (const float*)d_in[3];
    const int*   msk = (n_in >= 5) ? (const int*)d_in[4] : nullptr;
    float* out = (float*)d_out;

    const size_t smem = (size_t)SMEMF * sizeof(u32);   // 193536 B
    cudaFuncSetAttribute(fastmax_mma, cudaFuncAttributeMaxDynamicSharedMemorySize, (int)smem);
    fastmax_mma<<<NSUP * MAXC * Hh, THREADS, smem>>>(q, k, v, rpe, msk);
    finalize_kernel<<<(Hh * Nn * Dd / 4) / 256, 256>>>(msk, out);
}